// round 2
// baseline (speedup 1.0000x reference)
#include <cuda_runtime.h>
#include <stdint.h>

// Problem constants (fixed per reference source)
#define K_DIM 4096
#define N_DIM 4096
#define HASH_MASK 0xFFFFF        // HASH_SIZE = 2^20
#define P_CONST 56598313LL       // RzLinear.P (prime), hardcoded in reference

// Scratch: materialized weight matrix W[K][N] (64 MB) + hash residue tables.
__device__ float g_W[(size_t)K_DIM * N_DIM];
__device__ int   g_rowmod[K_DIM];   // (k*r3 + r1) % P
__device__ int   g_colmod[N_DIM];   // (n*r2) % P

// ---------------------------------------------------------------------------
// Kernel 1: per-row / per-col hash residues (the only 64-bit modulos).
// Self-detects whether random_numbers was materialized as int64 or int32:
// in the int64 layout rn64[0] == P exactly; in the int32 layout
// rn64[0] = P | (r1 << 32) which can only equal P if r1 == 0 (measure zero).
// ---------------------------------------------------------------------------
__global__ void hash_tables_kernel(const void* __restrict__ rn_raw) {
    const long long* rn64 = (const long long*)rn_raw;
    const int*       rn32 = (const int*)rn_raw;
    long long r1, r2, r3;
    if (rn64[0] == P_CONST) {           // int64 layout
        r1 = rn64[1]; r2 = rn64[2]; r3 = rn64[3];
    } else {                            // int32 layout
        r1 = rn32[1]; r2 = rn32[2]; r3 = rn32[3];
    }
    int i = blockIdx.x * blockDim.x + threadIdx.x;
    if (i < K_DIM) g_rowmod[i] = (int)(((long long)i * r3 + r1) % P_CONST);
    if (i < N_DIM) g_colmod[i] = (int)(((long long)i * r2) % P_CONST);
}

// ---------------------------------------------------------------------------
// Kernel 2: materialize W. Each thread: 1 row residue + 4 col residues,
// sum + conditional subtract (both residues < P so sum < 2P), mask, gather.
// Gathers are random within the 4 MB table (L2-resident); writes coalesced.
// ---------------------------------------------------------------------------
__global__ void gather_kernel(const float* __restrict__ hashed_weight) {
    const int P = (int)P_CONST;
    int t = blockIdx.x * blockDim.x + threadIdx.x;      // one thread per 4 n
    const int n_quads = N_DIM / 4;
    int k  = t / n_quads;
    int q  = t - k * n_quads;
    if (k >= K_DIM) return;

    const int base = g_rowmod[k];
    const int4 c = *(const int4*)(g_colmod + q * 4);

    int s0 = base + c.x; if (s0 >= P) s0 -= P;
    int s1 = base + c.y; if (s1 >= P) s1 -= P;
    int s2 = base + c.z; if (s2 >= P) s2 -= P;
    int s3 = base + c.w; if (s3 >= P) s3 -= P;

    float4 w;
    w.x = __ldg(hashed_weight + (s0 & HASH_MASK));
    w.y = __ldg(hashed_weight + (s1 & HASH_MASK));
    w.z = __ldg(hashed_weight + (s2 & HASH_MASK));
    w.w = __ldg(hashed_weight + (s3 & HASH_MASK));

    *(float4*)(g_W + (size_t)k * N_DIM + q * 4) = w;
}

// ---------------------------------------------------------------------------
// Kernel 3: fp32 SGEMM  C[M,N] = A[M,K] @ W[K,N] + bias
// 128x128 block tile, BK=16, 256 threads, 8x8 per-thread register tile.
// ---------------------------------------------------------------------------
#define BM 128
#define BN 128
#define BK 16
#define APAD 4   // As row pad -> reduces STS transpose conflicts

__global__ __launch_bounds__(256, 2)
void sgemm_kernel(const float* __restrict__ A,
                  const float* __restrict__ bias,
                  float* __restrict__ C) {
    __shared__ float As[BK][BM + APAD];
    __shared__ float Bs[BK][BN];

    const int tid = threadIdx.x;
    const int bx = blockIdx.x;   // N tile
    const int by = blockIdx.y;   // M tile

    // A-tile loader: 128 rows x 16 cols = 512 float4; 2 per thread.
    const int a_row  = tid >> 2;        // 0..63 (+64 second pass)
    const int a_col4 = tid & 3;         // which float4 within the 16 cols
    // B-tile loader: 16 rows x 128 cols = 512 float4; 2 per thread.
    const int b_row  = tid >> 5;        // 0..7 (+8 second pass)
    const int b_col4 = tid & 31;

    const float* Ablk = A + (size_t)(by * BM) * K_DIM;
    const float* Bblk = g_W + (size_t)(bx * BN);

    // compute mapping: 16x16 thread grid, 8x8 tile each
    const int tx = tid & 15;    // column group
    const int ty = tid >> 4;    // row group

    float acc[8][8];
    #pragma unroll
    for (int i = 0; i < 8; i++)
        #pragma unroll
        for (int j = 0; j < 8; j++) acc[i][j] = 0.0f;

    for (int k0 = 0; k0 < K_DIM; k0 += BK) {
        // load A tile (transposed into As[k][m])
        #pragma unroll
        for (int p = 0; p < 2; p++) {
            const int r = a_row + p * 64;
            float4 v = *(const float4*)(Ablk + (size_t)r * K_DIM + k0 + a_col4 * 4);
            As[a_col4 * 4 + 0][r] = v.x;
            As[a_col4 * 4 + 1][r] = v.y;
            As[a_col4 * 4 + 2][r] = v.z;
            As[a_col4 * 4 + 3][r] = v.w;
        }
        // load B tile (row-major)
        #pragma unroll
        for (int p = 0; p < 2; p++) {
            const int r = b_row + p * 8;
            *(float4*)&Bs[r][b_col4 * 4] =
                *(const float4*)(Bblk + (size_t)(k0 + r) * N_DIM + b_col4 * 4);
        }
        __syncthreads();

        #pragma unroll
        for (int kk = 0; kk < BK; kk++) {
            float4 a0 = *(const float4*)&As[kk][ty * 8];
            float4 a1 = *(const float4*)&As[kk][ty * 8 + 4];
            float4 b0 = *(const float4*)&Bs[kk][tx * 8];
            float4 b1 = *(const float4*)&Bs[kk][tx * 8 + 4];
            float ar[8] = {a0.x, a0.y, a0.z, a0.w, a1.x, a1.y, a1.z, a1.w};
            float br[8] = {b0.x, b0.y, b0.z, b0.w, b1.x, b1.y, b1.z, b1.w};
            #pragma unroll
            for (int i = 0; i < 8; i++)
                #pragma unroll
                for (int j = 0; j < 8; j++)
                    acc[i][j] = fmaf(ar[i], br[j], acc[i][j]);
        }
        __syncthreads();
    }

    // epilogue: add bias, vectorized stores
    const int col0 = bx * BN + tx * 8;
    float4 bv0 = *(const float4*)(bias + col0);
    float4 bv1 = *(const float4*)(bias + col0 + 4);
    #pragma unroll
    for (int i = 0; i < 8; i++) {
        const size_t row = (size_t)(by * BM + ty * 8 + i);
        float4 o0, o1;
        o0.x = acc[i][0] + bv0.x; o0.y = acc[i][1] + bv0.y;
        o0.z = acc[i][2] + bv0.z; o0.w = acc[i][3] + bv0.w;
        o1.x = acc[i][4] + bv1.x; o1.y = acc[i][5] + bv1.y;
        o1.z = acc[i][6] + bv1.z; o1.w = acc[i][7] + bv1.w;
        *(float4*)(C + row * N_DIM + col0)     = o0;
        *(float4*)(C + row * N_DIM + col0 + 4) = o1;
    }
}

// ---------------------------------------------------------------------------
// Launch. Inputs routed by element count (immune to metadata ordering):
//   4 elems -> random_numbers; 2^20 -> hashed_weight; 4096 -> bias;
//   largest -> x. Output f32 [M, N_DIM].
// ---------------------------------------------------------------------------
extern "C" void kernel_launch(void* const* d_in, const int* in_sizes, int n_in,
                              void* d_out, int out_size) {
    const float* x    = nullptr;
    const float* hw   = nullptr;
    const void*  rn   = nullptr;
    const float* bias = nullptr;

    long long max_sz = -1;
    int max_i = 0;
    for (int i = 0; i < n_in; i++) {
        if ((long long)in_sizes[i] > max_sz) { max_sz = in_sizes[i]; max_i = i; }
    }
    x = (const float*)d_in[max_i];
    for (int i = 0; i < n_in; i++) {
        if (i == max_i) continue;
        if (in_sizes[i] <= 8)                 rn   = d_in[i];           // 4 int64 (or int32)
        else if (in_sizes[i] == (1 << 20))    hw   = (const float*)d_in[i];
        else if (in_sizes[i] == N_DIM)        bias = (const float*)d_in[i];
    }

    float* out = (float*)d_out;
    const int M = (int)(max_sz / K_DIM);   // 8192

    hash_tables_kernel<<<(K_DIM + 255) / 256, 256>>>(rn);

    const int gather_threads = K_DIM * (N_DIM / 4);
    gather_kernel<<<(gather_threads + 255) / 256, 256>>>(hw);

    dim3 grid(N_DIM / BN, M / BM);
    sgemm_kernel<<<grid, 256>>>(x, bias, out);
}

// round 4
// speedup vs baseline: 1.9320x; 1.9320x over previous
#include <cuda_runtime.h>
#include <stdint.h>

// ============================================================================
// Problem constants (fixed per reference source)
// ============================================================================
#define K_DIM 4096
#define N_DIM 4096
#define M_MAX 8192
#define HASH_MASK 0xFFFFF        // HASH_SIZE = 2^20
#define P_CONST 56598313LL       // RzLinear.P (prime), hardcoded in reference

// Scratch (device globals; no allocation allowed)
__device__ uint32_t g_A[(size_t)M_MAX * K_DIM];   // x as tf32 bits, [M][K]
__device__ uint32_t g_B[(size_t)K_DIM * N_DIM];   // W as tf32 bits, [K][N]
__device__ int      g_rowmod[K_DIM];              // (k*r3 + r1) % P
__device__ int      g_colmod[N_DIM];              // (n*r2) % P

__device__ __forceinline__ uint32_t f32_to_tf32_rn(float f) {
    uint32_t u;
    asm("cvt.rna.tf32.f32 %0, %1;" : "=r"(u) : "f"(f));
    return u;
}
__device__ __forceinline__ uint32_t smem_u32(const void* p) {
    uint32_t a;
    asm("{ .reg .u64 t; cvta.to.shared.u64 t, %1; cvt.u32.u64 %0, t; }"
        : "=r"(a) : "l"(p));
    return a;
}
__device__ __forceinline__ void cp_async16(uint32_t dst, const void* src) {
    asm volatile("cp.async.cg.shared.global [%0], [%1], 16;"
                 :: "r"(dst), "l"(src) : "memory");
}
#define CP_COMMIT() asm volatile("cp.async.commit_group;" ::: "memory")
#define CP_WAIT1()  asm volatile("cp.async.wait_group 1;"  ::: "memory")
#define CP_WAIT0()  asm volatile("cp.async.wait_group 0;"  ::: "memory")

// m16n8k8 tf32 MMA (generic PTX, sm_80+; runs on the tensor pipe)
__device__ __forceinline__ void mma_tf32(float c[4], const uint32_t a[4],
                                         const uint32_t b[2]) {
    asm volatile(
        "mma.sync.aligned.m16n8k8.row.col.f32.tf32.tf32.f32 "
        "{%0,%1,%2,%3}, {%4,%5,%6,%7}, {%8,%9}, {%0,%1,%2,%3};"
        : "+f"(c[0]), "+f"(c[1]), "+f"(c[2]), "+f"(c[3])
        : "r"(a[0]), "r"(a[1]), "r"(a[2]), "r"(a[3]), "r"(b[0]), "r"(b[1]));
}

// ============================================================================
// Kernel 1: hash residue tables (self-detects int64 vs int32 materialization)
// ============================================================================
__global__ void hash_tables_kernel(const void* __restrict__ rn_raw) {
    const long long* rn64 = (const long long*)rn_raw;
    const int*       rn32 = (const int*)rn_raw;
    long long r1, r2, r3;
    if (rn64[0] == P_CONST) { r1 = rn64[1]; r2 = rn64[2]; r3 = rn64[3]; }
    else                    { r1 = rn32[1]; r2 = rn32[2]; r3 = rn32[3]; }
    int i = blockIdx.x * blockDim.x + threadIdx.x;
    if (i < K_DIM) g_rowmod[i] = (int)(((long long)i * r3 + r1) % P_CONST);
    if (i < N_DIM) g_colmod[i] = (int)(((long long)i * r2) % P_CONST);
}

// ============================================================================
// Kernel 2: gather W[k][n] from hash table, round to tf32 (RN)
// ============================================================================
__global__ void gather_kernel(const float* __restrict__ hw) {
    const int P = (int)P_CONST;
    int t = blockIdx.x * blockDim.x + threadIdx.x;      // one thread per 4 n
    const int nq = N_DIM / 4;
    int k = t / nq;
    int q = t - k * nq;
    if (k >= K_DIM) return;

    const int base = g_rowmod[k];
    const int4 c = *(const int4*)(g_colmod + q * 4);

    int s0 = base + c.x; if (s0 >= P) s0 -= P;
    int s1 = base + c.y; if (s1 >= P) s1 -= P;
    int s2 = base + c.z; if (s2 >= P) s2 -= P;
    int s3 = base + c.w; if (s3 >= P) s3 -= P;

    uint4 w;
    w.x = f32_to_tf32_rn(__ldg(hw + (s0 & HASH_MASK)));
    w.y = f32_to_tf32_rn(__ldg(hw + (s1 & HASH_MASK)));
    w.z = f32_to_tf32_rn(__ldg(hw + (s2 & HASH_MASK)));
    w.w = f32_to_tf32_rn(__ldg(hw + (s3 & HASH_MASK)));

    *(uint4*)(g_B + (size_t)k * N_DIM + q * 4) = w;
}

// Kernel 3: convert x -> tf32 (RN)
__global__ void cvt_a_kernel(const float* __restrict__ x, int total4) {
    int t = blockIdx.x * blockDim.x + threadIdx.x;
    if (t >= total4) return;
    float4 v = ((const float4*)x)[t];
    uint4 u;
    u.x = f32_to_tf32_rn(v.x);
    u.y = f32_to_tf32_rn(v.y);
    u.z = f32_to_tf32_rn(v.z);
    u.w = f32_to_tf32_rn(v.w);
    ((uint4*)g_A)[t] = u;
}

// ============================================================================
// Kernel 4: tf32 tensor-core GEMM via mma.sync
//   CTA tile 128x128, BK=32, 256 thr (8 warps, 2x4 -> warp tile 64x32),
//   2-stage cp.async double buffer.
// SMEM layouts (padded for conflict-free fragment LDS):
//   As: [128][36] words (row-major m x k, stride 36 -> banks 4*(l/4)+l%4)
//   Bs: [32][136] words (row-major k x n, stride 136 -> banks 8*(l%4)+l/4)
// ============================================================================
#define SA_W 36
#define SB_W 136
#define A_STAGE_B (128 * SA_W * 4)                 // 18432
#define B_STAGE_B (32 * SB_W * 4)                  // 17408
#define STAGE_B   (A_STAGE_B + B_STAGE_B)          // 35840
#define SMEM_GEMM (2 * STAGE_B)                    // 71680
#define NK        (K_DIM / 32)                     // 128

__device__ __forceinline__ void load_stage(uint32_t sbase, int stage,
                                           const uint32_t* gA, const uint32_t* gB,
                                           int m0, int n0, int k0, int tid) {
    const uint32_t a_s = sbase + stage * STAGE_B;
    const uint32_t b_s = a_s + A_STAGE_B;
    // A: 128 rows x 32 cols, 8 x 16B chunks per row, 2 threads per row
    {
        const int row = tid >> 1;
        const int cb  = (tid & 1) * 4;
        const uint32_t* src = gA + (size_t)(m0 + row) * K_DIM + k0 + cb * 4;
        const uint32_t dst = a_s + row * (SA_W * 4) + cb * 16;
        #pragma unroll
        for (int j = 0; j < 4; j++)
            cp_async16(dst + j * 16, src + j * 4);
    }
    // B: 32 rows x 128 cols, 32 x 16B chunks per row, 8 threads per row
    {
        const int row = tid >> 3;
        const int cb  = (tid & 7) * 4;
        const uint32_t* src = gB + (size_t)(k0 + row) * N_DIM + n0 + cb * 4;
        const uint32_t dst = b_s + row * (SB_W * 4) + cb * 16;
        #pragma unroll
        for (int j = 0; j < 4; j++)
            cp_async16(dst + j * 16, src + j * 4);
    }
}

__global__ __launch_bounds__(256, 2)
void gemm_mma_kernel(const float* __restrict__ bias, float* __restrict__ C) {
    extern __shared__ char smem[];
    const uint32_t sbase = smem_u32(smem);
    const int tid  = threadIdx.x;
    const int wid  = tid >> 5;
    const int lane = tid & 31;
    const int lq = lane >> 2;     // 0..7
    const int lr = lane & 3;      // 0..3
    const int wm = wid & 1;       // 2 m-groups of 64
    const int wn = wid >> 1;      // 4 n-groups of 32

    const int m_blk = blockIdx.y * 128;
    const int n_blk = blockIdx.x * 128;

    float acc[4][4][4];
    #pragma unroll
    for (int i = 0; i < 4; i++)
        #pragma unroll
        for (int j = 0; j < 4; j++)
            #pragma unroll
            for (int r = 0; r < 4; r++) acc[i][j][r] = 0.0f;

    load_stage(sbase, 0, g_A, g_B, m_blk, n_blk, 0, tid);
    CP_COMMIT();
    load_stage(sbase, 1, g_A, g_B, m_blk, n_blk, 32, tid);
    CP_COMMIT();

    for (int kt = 0; kt < NK; kt++) {
        CP_WAIT1();
        __syncthreads();

        const int st = kt & 1;
        const uint32_t* As = (const uint32_t*)(smem + st * STAGE_B);
        const uint32_t* Bs = (const uint32_t*)(smem + st * STAGE_B + A_STAGE_B);

        #pragma unroll
        for (int kk = 0; kk < 4; kk++) {
            const int k8 = kk * 8;
            uint32_t a[4][4];
            #pragma unroll
            for (int im = 0; im < 4; im++) {
                const uint32_t* ap =
                    As + (wm * 64 + im * 16 + lq) * SA_W + k8 + lr;
                a[im][0] = ap[0];
                a[im][1] = ap[8 * SA_W];
                a[im][2] = ap[4];
                a[im][3] = ap[8 * SA_W + 4];
            }
            uint32_t b[4][2];
            #pragma unroll
            for (int jn = 0; jn < 4; jn++) {
                const uint32_t* bp =
                    Bs + (k8 + lr) * SB_W + wn * 32 + jn * 8 + lq;
                b[jn][0] = bp[0];
                b[jn][1] = bp[4 * SB_W];
            }
            #pragma unroll
            for (int im = 0; im < 4; im++)
                #pragma unroll
                for (int jn = 0; jn < 4; jn++)
                    mma_tf32(acc[im][jn], a[im], b[jn]);
        }

        __syncthreads();
        if (kt + 2 < NK) {
            load_stage(sbase, st, g_A, g_B, m_blk, n_blk, (kt + 2) * 32, tid);
        }
        CP_COMMIT();   // keep group count in lockstep even when empty
    }
    CP_WAIT0();

    // epilogue: bias + direct stores (8B per thread-row-segment)
    #pragma unroll
    for (int jn = 0; jn < 4; jn++) {
        const int c0 = n_blk + wn * 32 + jn * 8 + 2 * lr;
        const float bx = __ldg(bias + c0);
        const float by = __ldg(bias + c0 + 1);
        #pragma unroll
        for (int im = 0; im < 4; im++) {
            const int r0 = m_blk + wm * 64 + im * 16 + lq;
            float2 v0, v1;
            v0.x = acc[im][jn][0] + bx; v0.y = acc[im][jn][1] + by;
            v1.x = acc[im][jn][2] + bx; v1.y = acc[im][jn][3] + by;
            *(float2*)(C + (size_t)r0 * N_DIM + c0)       = v0;
            *(float2*)(C + (size_t)(r0 + 8) * N_DIM + c0) = v1;
        }
    }
}

// ============================================================================
// Host launch. Inputs routed by element count (immune to metadata ordering):
//   <=8 elems -> random_numbers; 2^20 -> hashed_weight; 4096 -> bias;
//   largest -> x. Output f32 [M, N_DIM].
// ============================================================================
extern "C" void kernel_launch(void* const* d_in, const int* in_sizes, int n_in,
                              void* d_out, int out_size) {
    const float* x = nullptr; const float* hw = nullptr;
    const void* rn = nullptr; const float* bias = nullptr;
    long long max_sz = -1; int max_i = 0;
    for (int i = 0; i < n_in; i++)
        if ((long long)in_sizes[i] > max_sz) { max_sz = in_sizes[i]; max_i = i; }
    x = (const float*)d_in[max_i];
    for (int i = 0; i < n_in; i++) {
        if (i == max_i) continue;
        if (in_sizes[i] <= 8)              rn   = d_in[i];
        else if (in_sizes[i] == (1 << 20)) hw   = (const float*)d_in[i];
        else if (in_sizes[i] == N_DIM)     bias = (const float*)d_in[i];
    }
    float* out = (float*)d_out;
    const int M = (int)(max_sz / K_DIM);   // 8192

    hash_tables_kernel<<<(K_DIM + 255) / 256, 256>>>(rn);

    const int total4 = M * K_DIM / 4;
    cvt_a_kernel<<<(total4 + 255) / 256, 256>>>(x, total4);
    gather_kernel<<<(K_DIM * (N_DIM / 4) + 255) / 256, 256>>>(hw);

    static bool smem_set = false;
    if (!smem_set) {
        cudaFuncSetAttribute(gemm_mma_kernel,
                             cudaFuncAttributeMaxDynamicSharedMemorySize,
                             SMEM_GEMM);
        smem_set = true;
    }
    dim3 grid(N_DIM / 128, M / 128);
    gemm_mma_kernel<<<grid, 256, SMEM_GEMM>>>(bias, out);
}

// round 5
// speedup vs baseline: 3.0891x; 1.5989x over previous
#include <cuda_runtime.h>
#include <stdint.h>

// ============================================================================
// Problem constants (fixed per reference source)
// ============================================================================
#define K_DIM 4096
#define N_DIM 4096
#define M_MAX 8192
#define HASH_MASK 0xFFFFF        // HASH_SIZE = 2^20
#define P_CONST 56598313LL       // RzLinear.P (prime), hardcoded in reference

// Scratch (device globals; no allocation allowed)
// g_A: [M][K] tf32, per-8 interleave: out[2*lr+j] = in[lr+4*j]  (pairs k,k+4)
// g_B: [K/32][16][N][2] tf32 pair-major: word ((kb*16+kp)*N + n)*2 + j
//      kp = (k%4) + 4*((k%32)/8),  j = (k%8)/4
__device__ uint32_t g_A[(size_t)M_MAX * K_DIM];
__device__ uint32_t g_B[(size_t)K_DIM * N_DIM];
__device__ int      g_rowmod[K_DIM];              // (k*r3 + r1) % P
__device__ int      g_colmod[N_DIM];              // (n*r2) % P

__device__ __forceinline__ uint32_t f32_to_tf32_rn(float f) {
    uint32_t u;
    asm("cvt.rna.tf32.f32 %0, %1;" : "=r"(u) : "f"(f));
    return u;
}
__device__ __forceinline__ uint32_t smem_u32(const void* p) {
    uint32_t a;
    asm("{ .reg .u64 t; cvta.to.shared.u64 t, %1; cvt.u32.u64 %0, t; }"
        : "=r"(a) : "l"(p));
    return a;
}
__device__ __forceinline__ void cp_async16(uint32_t dst, const void* src) {
    asm volatile("cp.async.cg.shared.global [%0], [%1], 16;"
                 :: "r"(dst), "l"(src) : "memory");
}
#define CP_COMMIT() asm volatile("cp.async.commit_group;" ::: "memory")
#define CP_WAIT2()  asm volatile("cp.async.wait_group 2;"  ::: "memory")
#define CP_WAIT0()  asm volatile("cp.async.wait_group 0;"  ::: "memory")

// m16n8k8 tf32 MMA (generic PTX, sm_80+; runs on the tensor pipe)
__device__ __forceinline__ void mma_tf32(float c[4], uint32_t a0, uint32_t a1,
                                         uint32_t a2, uint32_t a3,
                                         uint32_t b0, uint32_t b1) {
    asm volatile(
        "mma.sync.aligned.m16n8k8.row.col.f32.tf32.tf32.f32 "
        "{%0,%1,%2,%3}, {%4,%5,%6,%7}, {%8,%9}, {%0,%1,%2,%3};"
        : "+f"(c[0]), "+f"(c[1]), "+f"(c[2]), "+f"(c[3])
        : "r"(a0), "r"(a1), "r"(a2), "r"(a3), "r"(b0), "r"(b1));
}

// ============================================================================
// Kernel 1: hash residue tables (self-detects int64 vs int32 materialization)
// ============================================================================
__global__ void hash_tables_kernel(const void* __restrict__ rn_raw) {
    const long long* rn64 = (const long long*)rn_raw;
    const int*       rn32 = (const int*)rn_raw;
    long long r1, r2, r3;
    if (rn64[0] == P_CONST) { r1 = rn64[1]; r2 = rn64[2]; r3 = rn64[3]; }
    else                    { r1 = rn32[1]; r2 = rn32[2]; r3 = rn32[3]; }
    int i = blockIdx.x * blockDim.x + threadIdx.x;
    if (i < K_DIM) g_rowmod[i] = (int)(((long long)i * r3 + r1) % P_CONST);
    if (i < N_DIM) g_colmod[i] = (int)(((long long)i * r2) % P_CONST);
}

// ============================================================================
// Kernel 2: gather W into pair-major tf32 layout
//   thread t -> one uint4 = { (k0,n), (k1,n), (k0,n+1), (k1,n+1) }
//   where t = (kb*16 + kp)*(N/2) + n/2,  k0 = kb*32 + (kp>>2)*8 + (kp&3),
//   k1 = k0 + 4. Fully coalesced 16B writes.
// ============================================================================
__global__ void gather_kernel(const float* __restrict__ hw) {
    const int P = (int)P_CONST;
    const int t = blockIdx.x * blockDim.x + threadIdx.x;
    const int total = (K_DIM / 32) * 16 * (N_DIM / 2);
    if (t >= total) return;

    const int n2  = t & (N_DIM / 2 - 1);
    const int row = t >> 11;            // (kb*16 + kp)
    const int kp  = row & 15;
    const int kb  = row >> 4;
    const int k0  = kb * 32 + (kp >> 2) * 8 + (kp & 3);
    const int n   = n2 * 2;

    const int rm0 = g_rowmod[k0];
    const int rm1 = g_rowmod[k0 + 4];
    const int c0  = g_colmod[n];
    const int c1  = g_colmod[n + 1];

    int s00 = rm0 + c0; if (s00 >= P) s00 -= P;
    int s10 = rm1 + c0; if (s10 >= P) s10 -= P;
    int s01 = rm0 + c1; if (s01 >= P) s01 -= P;
    int s11 = rm1 + c1; if (s11 >= P) s11 -= P;

    uint4 w;
    w.x = f32_to_tf32_rn(__ldg(hw + (s00 & HASH_MASK)));
    w.y = f32_to_tf32_rn(__ldg(hw + (s10 & HASH_MASK)));
    w.z = f32_to_tf32_rn(__ldg(hw + (s01 & HASH_MASK)));
    w.w = f32_to_tf32_rn(__ldg(hw + (s11 & HASH_MASK)));

    ((uint4*)g_B)[t] = w;
}

// ============================================================================
// Kernel 3: x -> tf32 with per-8 (k, k+4) pair interleave
//   out8 = [in0,in4,in1,in5,in2,in6,in3,in7]
// ============================================================================
__global__ void cvt_a_kernel(const float* __restrict__ x, int total8) {
    int t = blockIdx.x * blockDim.x + threadIdx.x;
    if (t >= total8) return;
    float4 v0 = ((const float4*)x)[2 * t];
    float4 v1 = ((const float4*)x)[2 * t + 1];
    uint4 o0, o1;
    o0.x = f32_to_tf32_rn(v0.x); o0.y = f32_to_tf32_rn(v1.x);
    o0.z = f32_to_tf32_rn(v0.y); o0.w = f32_to_tf32_rn(v1.y);
    o1.x = f32_to_tf32_rn(v0.z); o1.y = f32_to_tf32_rn(v1.z);
    o1.z = f32_to_tf32_rn(v0.w); o1.w = f32_to_tf32_rn(v1.w);
    ((uint4*)g_A)[2 * t]     = o0;
    ((uint4*)g_A)[2 * t + 1] = o1;
}

// ============================================================================
// Kernel 4: tf32 tensor-core GEMM via mma.sync
//   CTA tile 128x256, BK=32, 256 thr (8 warps 2x4 -> warp tile 64x64),
//   3-stage cp.async pipeline, all fragment loads LDS.64 (paired layout).
// SMEM strides chosen ≡ 8 (mod 32) words -> conflict-free 64-bit accesses:
//   As: [128 rows m][40 words]   (32 data words, per-8 pair-interleaved)
//   Bs: [16 rows kp][520 words]  (512 data words = 256 n-pairs)
// ============================================================================
#define SA_W 40
#define SB_W 520
#define A_STAGE_B (128 * SA_W * 4)                 // 20480
#define B_STAGE_B (16 * SB_W * 4)                  // 33280
#define STAGE_B   (A_STAGE_B + B_STAGE_B)          // 53760
#define NSTAGE 3
#define SMEM_GEMM (NSTAGE * STAGE_B)               // 161280
#define NK        (K_DIM / 32)                     // 128

__device__ __forceinline__ void load_stage(uint32_t sbase, int stage,
                                           int m0, int n0, int kt, int tid) {
    const uint32_t a_s = sbase + stage * STAGE_B;
    const uint32_t b_s = a_s + A_STAGE_B;
    // A: 128 rows x 32 words; 8 chunks/row, 2 threads/row (4 chunks each)
    {
        const int row = tid >> 1;
        const int cb  = (tid & 1) * 4;
        const uint32_t* src = g_A + (size_t)(m0 + row) * K_DIM + kt * 32 + cb * 4;
        const uint32_t dst = a_s + row * (SA_W * 4) + cb * 16;
        #pragma unroll
        for (int j = 0; j < 4; j++)
            cp_async16(dst + j * 16, src + j * 4);
    }
    // B: 16 rows (kp) x 512 words; 128 chunks/row, 16 threads/row (8 each)
    {
        const int r = tid >> 4;
        const int c = tid & 15;
        const uint32_t* src =
            g_B + ((size_t)(kt * 16 + r) * N_DIM + n0) * 2 + c * 4;
        const uint32_t dst = b_s + r * (SB_W * 4) + c * 16;
        #pragma unroll
        for (int j = 0; j < 8; j++)
            cp_async16(dst + j * 256, src + j * 64);
    }
}

__global__ __launch_bounds__(256, 1)
void gemm_mma_kernel(const float* __restrict__ bias, float* __restrict__ C) {
    extern __shared__ char smem[];
    const uint32_t sbase = smem_u32(smem);
    const int tid  = threadIdx.x;
    const int wid  = tid >> 5;
    const int lane = tid & 31;
    const int lq = lane >> 2;     // 0..7
    const int lr = lane & 3;      // 0..3
    const int wm = wid & 1;       // 2 m-halves of 64
    const int wn = wid >> 1;      // 4 n-quarters of 64

    const int m_blk = blockIdx.y * 128;
    const int n_blk = blockIdx.x * 256;

    float acc[4][8][4];
    #pragma unroll
    for (int i = 0; i < 4; i++)
        #pragma unroll
        for (int j = 0; j < 8; j++)
            #pragma unroll
            for (int r = 0; r < 4; r++) acc[i][j][r] = 0.0f;

    load_stage(sbase, 0, m_blk, n_blk, 0, tid); CP_COMMIT();
    load_stage(sbase, 1, m_blk, n_blk, 1, tid); CP_COMMIT();
    load_stage(sbase, 2, m_blk, n_blk, 2, tid); CP_COMMIT();

    int st = 0;
    for (int kt = 0; kt < NK; kt++) {
        CP_WAIT2();
        __syncthreads();

        const uint32_t* As = (const uint32_t*)(smem + st * STAGE_B);
        const uint32_t* Bs = (const uint32_t*)(smem + st * STAGE_B + A_STAGE_B);

        #pragma unroll
        for (int kk = 0; kk < 4; kk++) {
            const int kpo = (lr + 4 * kk) * 2;
            // A fragments: 4 m-steps, 2x LDS.64 each
            uint2 a_lo[4], a_hi[4];
            #pragma unroll
            for (int im = 0; im < 4; im++) {
                const uint32_t* ap =
                    As + (wm * 64 + im * 16 + lq) * SA_W + kpo;
                a_lo[im] = *(const uint2*)ap;               // {a0, a2}
                a_hi[im] = *(const uint2*)(ap + 8 * SA_W);  // {a1, a3}
            }
            // B fragments: 8 n-steps, 1x LDS.64 each
            uint2 b[8];
            #pragma unroll
            for (int jn = 0; jn < 8; jn++) {
                b[jn] = *(const uint2*)
                    (Bs + (lr + 4 * kk) * SB_W + (wn * 64 + jn * 8 + lq) * 2);
            }
            #pragma unroll
            for (int im = 0; im < 4; im++)
                #pragma unroll
                for (int jn = 0; jn < 8; jn++)
                    mma_tf32(acc[im][jn],
                             a_lo[im].x, a_hi[im].x, a_lo[im].y, a_hi[im].y,
                             b[jn].x, b[jn].y);
        }

        __syncthreads();
        if (kt + 3 < NK)
            load_stage(sbase, st, m_blk, n_blk, kt + 3, tid);
        CP_COMMIT();   // keep group count in lockstep even when empty
        st = (st == NSTAGE - 1) ? 0 : st + 1;
    }
    CP_WAIT0();

    // epilogue: bias + direct stores
    #pragma unroll
    for (int jn = 0; jn < 8; jn++) {
        const int c0 = n_blk + wn * 64 + jn * 8 + 2 * lr;
        const float bx = __ldg(bias + c0);
        const float by = __ldg(bias + c0 + 1);
        #pragma unroll
        for (int im = 0; im < 4; im++) {
            const int r0 = m_blk + wm * 64 + im * 16 + lq;
            float2 v0, v1;
            v0.x = acc[im][jn][0] + bx; v0.y = acc[im][jn][1] + by;
            v1.x = acc[im][jn][2] + bx; v1.y = acc[im][jn][3] + by;
            *(float2*)(C + (size_t)r0 * N_DIM + c0)       = v0;
            *(float2*)(C + (size_t)(r0 + 8) * N_DIM + c0) = v1;
        }
    }
}

// ============================================================================
// Host launch. Inputs routed by element count (immune to metadata ordering):
//   <=8 elems -> random_numbers; 2^20 -> hashed_weight; 4096 -> bias;
//   largest -> x. Output f32 [M, N_DIM].
// ============================================================================
extern "C" void kernel_launch(void* const* d_in, const int* in_sizes, int n_in,
                              void* d_out, int out_size) {
    const float* x = nullptr; const float* hw = nullptr;
    const void* rn = nullptr; const float* bias = nullptr;
    long long max_sz = -1; int max_i = 0;
    for (int i = 0; i < n_in; i++)
        if ((long long)in_sizes[i] > max_sz) { max_sz = in_sizes[i]; max_i = i; }
    x = (const float*)d_in[max_i];
    for (int i = 0; i < n_in; i++) {
        if (i == max_i) continue;
        if (in_sizes[i] <= 8)              rn   = d_in[i];
        else if (in_sizes[i] == (1 << 20)) hw   = (const float*)d_in[i];
        else if (in_sizes[i] == N_DIM)     bias = (const float*)d_in[i];
    }
    float* out = (float*)d_out;
    const int M = (int)(max_sz / K_DIM);   // 8192

    hash_tables_kernel<<<(K_DIM + 255) / 256, 256>>>(rn);

    const int total8 = M * K_DIM / 8;
    cvt_a_kernel<<<(total8 + 255) / 256, 256>>>(x, total8);

    const int gthreads = (K_DIM / 32) * 16 * (N_DIM / 2);
    gather_kernel<<<(gthreads + 255) / 256, 256>>>(hw);

    static bool smem_set = false;
    if (!smem_set) {
        cudaFuncSetAttribute(gemm_mma_kernel,
                             cudaFuncAttributeMaxDynamicSharedMemorySize,
                             SMEM_GEMM);
        smem_set = true;
    }
    dim3 grid(N_DIM / 256, M / 128);
    gemm_mma_kernel<<<grid, 256, SMEM_GEMM>>>(bias, out);
}

// round 6
// speedup vs baseline: 3.3298x; 1.0779x over previous
#include <cuda_runtime.h>
#include <stdint.h>

// ============================================================================
// Problem constants (fixed per reference source)
// ============================================================================
#define K_DIM 4096
#define N_DIM 4096
#define M_MAX 8192
#define HASH_MASK 0xFFFFF        // HASH_SIZE = 2^20
#define P_CONST 56598313LL       // RzLinear.P (prime), hardcoded in reference

// Scratch (device globals; no allocation allowed)
// g_A: [M][K] tf32, per-8 interleave: out[2*lr+j] = in[lr+4*j]  (pairs k,k+4)
// g_B: [K/32][16][N][2] tf32 pair-major: word ((kb*16+kp)*N + n)*2 + j
//      kp = (k%4) + 4*((k%32)/8),  j = (k%8)/4
__device__ uint32_t g_A[(size_t)M_MAX * K_DIM];
__device__ uint32_t g_B[(size_t)K_DIM * N_DIM];
__device__ int      g_rowmod[K_DIM];              // (k*r3 + r1) % P
__device__ int      g_colmod[N_DIM];              // (n*r2) % P

__device__ __forceinline__ uint32_t f32_to_tf32_rn(float f) {
    uint32_t u;
    asm("cvt.rna.tf32.f32 %0, %1;" : "=r"(u) : "f"(f));
    return u;
}
__device__ __forceinline__ uint32_t smem_u32(const void* p) {
    uint32_t a;
    asm("{ .reg .u64 t; cvta.to.shared.u64 t, %1; cvt.u32.u64 %0, t; }"
        : "=r"(a) : "l"(p));
    return a;
}
__device__ __forceinline__ void cp_async16(uint32_t dst, const void* src) {
    asm volatile("cp.async.cg.shared.global [%0], [%1], 16;"
                 :: "r"(dst), "l"(src) : "memory");
}
#define CP_COMMIT() asm volatile("cp.async.commit_group;" ::: "memory")
#define CP_WAIT2()  asm volatile("cp.async.wait_group 2;"  ::: "memory")
#define CP_WAIT0()  asm volatile("cp.async.wait_group 0;"  ::: "memory")

// m16n8k8 tf32 MMA (generic PTX, sm_80+; runs on the tensor pipe)
__device__ __forceinline__ void mma_tf32(float c[4], uint32_t a0, uint32_t a1,
                                         uint32_t a2, uint32_t a3,
                                         uint32_t b0, uint32_t b1) {
    asm volatile(
        "mma.sync.aligned.m16n8k8.row.col.f32.tf32.tf32.f32 "
        "{%0,%1,%2,%3}, {%4,%5,%6,%7}, {%8,%9}, {%0,%1,%2,%3};"
        : "+f"(c[0]), "+f"(c[1]), "+f"(c[2]), "+f"(c[3])
        : "r"(a0), "r"(a1), "r"(a2), "r"(a3), "r"(b0), "r"(b1));
}

// ============================================================================
// Kernel 1: hash residue tables (self-detects int64 vs int32 materialization)
// ============================================================================
__global__ void hash_tables_kernel(const void* __restrict__ rn_raw) {
    const long long* rn64 = (const long long*)rn_raw;
    const int*       rn32 = (const int*)rn_raw;
    long long r1, r2, r3;
    if (rn64[0] == P_CONST) { r1 = rn64[1]; r2 = rn64[2]; r3 = rn64[3]; }
    else                    { r1 = rn32[1]; r2 = rn32[2]; r3 = rn32[3]; }
    int i = blockIdx.x * blockDim.x + threadIdx.x;
    if (i < K_DIM) g_rowmod[i] = (int)(((long long)i * r3 + r1) % P_CONST);
    if (i < N_DIM) g_colmod[i] = (int)(((long long)i * r2) % P_CONST);
}

// ============================================================================
// Kernel 2: gather W into pair-major tf32 layout
//   thread t -> one uint4 = { (k0,n), (k1,n), (k0,n+1), (k1,n+1) }
//   where t = (kb*16 + kp)*(N/2) + n/2,  k0 = kb*32 + (kp>>2)*8 + (kp&3),
//   k1 = k0 + 4. Fully coalesced 16B writes.
// ============================================================================
__global__ void gather_kernel(const float* __restrict__ hw) {
    const int P = (int)P_CONST;
    const int t = blockIdx.x * blockDim.x + threadIdx.x;
    const int total = (K_DIM / 32) * 16 * (N_DIM / 2);
    if (t >= total) return;

    const int n2  = t & (N_DIM / 2 - 1);
    const int row = t >> 11;            // (kb*16 + kp)
    const int kp  = row & 15;
    const int kb  = row >> 4;
    const int k0  = kb * 32 + (kp >> 2) * 8 + (kp & 3);
    const int n   = n2 * 2;

    const int rm0 = g_rowmod[k0];
    const int rm1 = g_rowmod[k0 + 4];
    const int c0  = g_colmod[n];
    const int c1  = g_colmod[n + 1];

    int s00 = rm0 + c0; if (s00 >= P) s00 -= P;
    int s10 = rm1 + c0; if (s10 >= P) s10 -= P;
    int s01 = rm0 + c1; if (s01 >= P) s01 -= P;
    int s11 = rm1 + c1; if (s11 >= P) s11 -= P;

    uint4 w;
    w.x = f32_to_tf32_rn(__ldg(hw + (s00 & HASH_MASK)));
    w.y = f32_to_tf32_rn(__ldg(hw + (s10 & HASH_MASK)));
    w.z = f32_to_tf32_rn(__ldg(hw + (s01 & HASH_MASK)));
    w.w = f32_to_tf32_rn(__ldg(hw + (s11 & HASH_MASK)));

    ((uint4*)g_B)[t] = w;
}

// ============================================================================
// Kernel 3: x -> tf32 with per-8 (k, k+4) pair interleave
//   out8 = [in0,in4,in1,in5,in2,in6,in3,in7]
// ============================================================================
__global__ void cvt_a_kernel(const float* __restrict__ x, int total8) {
    int t = blockIdx.x * blockDim.x + threadIdx.x;
    if (t >= total8) return;
    float4 v0 = ((const float4*)x)[2 * t];
    float4 v1 = ((const float4*)x)[2 * t + 1];
    uint4 o0, o1;
    o0.x = f32_to_tf32_rn(v0.x); o0.y = f32_to_tf32_rn(v1.x);
    o0.z = f32_to_tf32_rn(v0.y); o0.w = f32_to_tf32_rn(v1.y);
    o1.x = f32_to_tf32_rn(v0.z); o1.y = f32_to_tf32_rn(v1.z);
    o1.z = f32_to_tf32_rn(v0.w); o1.w = f32_to_tf32_rn(v1.w);
    ((uint4*)g_A)[2 * t]     = o0;
    ((uint4*)g_A)[2 * t + 1] = o1;
}

// ============================================================================
// Kernel 4: tf32 tensor-core GEMM via mma.sync
//   CTA tile 128x256, BK=32, 512 thr (16 warps 2x8 -> warp tile 64x32),
//   3-stage cp.async pipeline, all fragment loads LDS.64 (paired layout).
//   4 warps per SMSP -> LDS latency hidden behind other warps' MMAs.
// SMEM strides ≡ 8 (mod 32) words -> conflict-free 64-bit accesses:
//   As: [128 rows m][40 words]   (32 data words, per-8 pair-interleaved)
//   Bs: [16 rows kp][520 words]  (512 data words = 256 n-pairs)
// ============================================================================
#define SA_W 40
#define SB_W 520
#define A_STAGE_B (128 * SA_W * 4)                 // 20480
#define B_STAGE_B (16 * SB_W * 4)                  // 33280
#define STAGE_B   (A_STAGE_B + B_STAGE_B)          // 53760
#define NSTAGE 3
#define SMEM_GEMM (NSTAGE * STAGE_B)               // 161280
#define NK        (K_DIM / 32)                     // 128

__device__ __forceinline__ void load_stage(uint32_t sbase, int stage,
                                           int m0, int n0, int kt, int tid) {
    const uint32_t a_s = sbase + stage * STAGE_B;
    const uint32_t b_s = a_s + A_STAGE_B;
    // A: 128 rows x 8 chunks (16B); 4 threads/row, 2 chunks each
    {
        const int row = tid >> 2;
        const int cb  = (tid & 3) * 2;
        const uint32_t* src = g_A + (size_t)(m0 + row) * K_DIM + kt * 32 + cb * 4;
        const uint32_t dst = a_s + row * (SA_W * 4) + cb * 16;
        cp_async16(dst,      src);
        cp_async16(dst + 16, src + 4);
    }
    // B: 16 rows (kp) x 128 chunks; 32 threads/row, 4 chunks each (stride 32)
    {
        const int r = tid >> 5;
        const int c = tid & 31;
        const uint32_t* src =
            g_B + ((size_t)(kt * 16 + r) * N_DIM + n0) * 2 + c * 4;
        const uint32_t dst = b_s + r * (SB_W * 4) + c * 16;
        #pragma unroll
        for (int j = 0; j < 4; j++)
            cp_async16(dst + j * 512, src + j * 128);
    }
}

__global__ __launch_bounds__(512, 1)
void gemm_mma_kernel(const float* __restrict__ bias, float* __restrict__ C) {
    extern __shared__ char smem[];
    const uint32_t sbase = smem_u32(smem);
    const int tid  = threadIdx.x;
    const int wid  = tid >> 5;
    const int lane = tid & 31;
    const int lq = lane >> 2;     // 0..7
    const int lr = lane & 3;      // 0..3
    const int wm = wid & 1;       // 2 m-halves of 64
    const int wn = wid >> 1;      // 8 n-slices of 32

    const int m_blk = blockIdx.y * 128;
    const int n_blk = blockIdx.x * 256;

    float acc[4][4][4];
    #pragma unroll
    for (int i = 0; i < 4; i++)
        #pragma unroll
        for (int j = 0; j < 4; j++)
            #pragma unroll
            for (int r = 0; r < 4; r++) acc[i][j][r] = 0.0f;

    load_stage(sbase, 0, m_blk, n_blk, 0, tid); CP_COMMIT();
    load_stage(sbase, 1, m_blk, n_blk, 1, tid); CP_COMMIT();
    load_stage(sbase, 2, m_blk, n_blk, 2, tid); CP_COMMIT();

    int st = 0;
    for (int kt = 0; kt < NK; kt++) {
        CP_WAIT2();
        __syncthreads();

        const uint32_t* As = (const uint32_t*)(smem + st * STAGE_B);
        const uint32_t* Bs = (const uint32_t*)(smem + st * STAGE_B + A_STAGE_B);

        #pragma unroll
        for (int kk = 0; kk < 4; kk++) {
            const int kpo = (lr + 4 * kk) * 2;
            // A fragments: 4 m-steps, 2x LDS.64 each
            uint2 a_lo[4], a_hi[4];
            #pragma unroll
            for (int im = 0; im < 4; im++) {
                const uint32_t* ap =
                    As + (wm * 64 + im * 16 + lq) * SA_W + kpo;
                a_lo[im] = *(const uint2*)ap;               // {a0, a2}
                a_hi[im] = *(const uint2*)(ap + 8 * SA_W);  // {a1, a3}
            }
            // B fragments: 4 n-steps, 1x LDS.64 each
            uint2 b[4];
            #pragma unroll
            for (int jn = 0; jn < 4; jn++) {
                b[jn] = *(const uint2*)
                    (Bs + (lr + 4 * kk) * SB_W + (wn * 32 + jn * 8 + lq) * 2);
            }
            #pragma unroll
            for (int im = 0; im < 4; im++)
                #pragma unroll
                for (int jn = 0; jn < 4; jn++)
                    mma_tf32(acc[im][jn],
                             a_lo[im].x, a_hi[im].x, a_lo[im].y, a_hi[im].y,
                             b[jn].x, b[jn].y);
        }

        __syncthreads();
        if (kt + 3 < NK)
            load_stage(sbase, st, m_blk, n_blk, kt + 3, tid);
        CP_COMMIT();   // keep group count in lockstep even when empty
        st = (st == NSTAGE - 1) ? 0 : st + 1;
    }
    CP_WAIT0();

    // epilogue: bias + direct stores
    #pragma unroll
    for (int jn = 0; jn < 4; jn++) {
        const int c0 = n_blk + wn * 32 + jn * 8 + 2 * lr;
        const float bx = __ldg(bias + c0);
        const float by = __ldg(bias + c0 + 1);
        #pragma unroll
        for (int im = 0; im < 4; im++) {
            const int r0 = m_blk + wm * 64 + im * 16 + lq;
            float2 v0, v1;
            v0.x = acc[im][jn][0] + bx; v0.y = acc[im][jn][1] + by;
            v1.x = acc[im][jn][2] + bx; v1.y = acc[im][jn][3] + by;
            *(float2*)(C + (size_t)r0 * N_DIM + c0)       = v0;
            *(float2*)(C + (size_t)(r0 + 8) * N_DIM + c0) = v1;
        }
    }
}

// ============================================================================
// Host launch. Inputs routed by element count (immune to metadata ordering):
//   <=8 elems -> random_numbers; 2^20 -> hashed_weight; 4096 -> bias;
//   largest -> x. Output f32 [M, N_DIM].
// ============================================================================
extern "C" void kernel_launch(void* const* d_in, const int* in_sizes, int n_in,
                              void* d_out, int out_size) {
    const float* x = nullptr; const float* hw = nullptr;
    const void* rn = nullptr; const float* bias = nullptr;
    long long max_sz = -1; int max_i = 0;
    for (int i = 0; i < n_in; i++)
        if ((long long)in_sizes[i] > max_sz) { max_sz = in_sizes[i]; max_i = i; }
    x = (const float*)d_in[max_i];
    for (int i = 0; i < n_in; i++) {
        if (i == max_i) continue;
        if (in_sizes[i] <= 8)              rn   = d_in[i];
        else if (in_sizes[i] == (1 << 20)) hw   = (const float*)d_in[i];
        else if (in_sizes[i] == N_DIM)     bias = (const float*)d_in[i];
    }
    float* out = (float*)d_out;
    const int M = (int)(max_sz / K_DIM);   // 8192

    hash_tables_kernel<<<(K_DIM + 255) / 256, 256>>>(rn);

    const int total8 = M * K_DIM / 8;
    cvt_a_kernel<<<(total8 + 255) / 256, 256>>>(x, total8);

    const int gthreads = (K_DIM / 32) * 16 * (N_DIM / 2);
    gather_kernel<<<(gthreads + 255) / 256, 256>>>(hw);

    static bool smem_set = false;
    if (!smem_set) {
        cudaFuncSetAttribute(gemm_mma_kernel,
                             cudaFuncAttributeMaxDynamicSharedMemorySize,
                             SMEM_GEMM);
        smem_set = true;
    }
    dim3 grid(N_DIM / 256, M / 128);
    gemm_mma_kernel<<<grid, 512, SMEM_GEMM>>>(bias, out);
}